// round 16
// baseline (speedup 1.0000x reference)
#include <cuda_runtime.h>
#include <cuda_bf16.h>
#include <cstdint>

// Problem constants
#define NN 50000
#define EE 800000
#define DD 128
#define LL 3
#define BB 256
#define BN_EPS 1e-5f
#define GEMM_TILES ((NN + 63) / 64)    // 782 BM=64 tiles
#define PAIRS 148
#define PERSIST_GRID (PAIRS * 2)       // 296: CTA pair (even: cols 0-63, odd: 64-127)

// smem layout: A 64x128 bf16 swizzled (16KB hi + 16KB lo), B-half 128x64 bf16
// (16KB hi + 16KB lo, 128B row pitch), fp32 A stage 64 rows x 528B pitch.
#define SM_AHI 0
#define SM_ALO 16384
#define SM_BHI 32768
#define SM_BLO 49152
#define SM_STAGE 65536
#define STAGE_PITCH 528
#define SMEM_TOT (65536 + 64 * STAGE_PITCH)   // 99328

// ---------------- scratch (static device globals; no allocation) ----------------
__device__ float g_bufA[(size_t)NN * DD];   // z: raw pre-BN2 layer output
__device__ float g_bufB[(size_t)NN * DD];   // agg (input to GEMM1)
__device__ float g_bufC[(size_t)NN * DD];   // y: raw pre-BN1 hidden
__device__ int   g_deg[NN];
__device__ int   g_rowstart[NN];
__device__ int   g_cursor[NN];
__device__ int   g_col[EE];                 // BYTE offsets (src*512)
__device__ int   g_total;
__device__ float g_acc_s[DD];               // BN stat accumulators (zero-init; self-reset)
__device__ float g_acc_q[DD];
__device__ int   g_done;                    // last-CTA counter (zero-init; self-reset)
__device__ float g_scale1[DD];
__device__ float g_shift1[DD];
__device__ float g_scale2[DD];
__device__ float g_shift2[DD];
// prepared weights: [layer*2+which][hi/lo][32KB tile as uint4], swizzled [k][n] layout
__device__ uint4 g_wt[6][2][2048];

// ---------------- helpers ----------------
__device__ __forceinline__ uint32_t smem_u32(const void* p) {
    uint32_t a;
    asm("{ .reg .u64 t; cvta.to.shared.u64 t, %1; cvt.u32.u64 %0, t; }" : "=r"(a) : "l"(p));
    return a;
}

// byte offset inside a [rows]x128 bf16 tile (256B rows, 16B chunks, xor swizzle)
__device__ __forceinline__ uint32_t swz(int row, int col8) {
    int chunk = col8 >> 3;
    return (uint32_t)(row * 256 + ((chunk ^ (row & 7)) << 4));
}

// split fp32 pair -> bf16x2 hi + bf16x2 lo
__device__ __forceinline__ void split2(float a, float b, uint32_t& hi, uint32_t& lo) {
    __nv_bfloat162 h = __floats2bfloat162_rn(a, b);
    uint32_t uh = *reinterpret_cast<uint32_t*>(&h);
    float ra = __uint_as_float((uh & 0xFFFFu) << 16);
    float rb = __uint_as_float(uh & 0xFFFF0000u);
    __nv_bfloat162 l = __floats2bfloat162_rn(a - ra, b - rb);
    hi = uh;
    lo = *reinterpret_cast<uint32_t*>(&l);
}

__device__ __forceinline__ void ldsm_x4(uint32_t addr, uint32_t& r0, uint32_t& r1,
                                        uint32_t& r2, uint32_t& r3) {
    asm volatile("ldmatrix.sync.aligned.m8n8.x4.shared.b16 {%0,%1,%2,%3}, [%4];"
                 : "=r"(r0), "=r"(r1), "=r"(r2), "=r"(r3) : "r"(addr));
}

__device__ __forceinline__ void ldsm_x4_t(uint32_t addr, uint32_t& r0, uint32_t& r1,
                                          uint32_t& r2, uint32_t& r3) {
    asm volatile("ldmatrix.sync.aligned.m8n8.x4.trans.shared.b16 {%0,%1,%2,%3}, [%4];"
                 : "=r"(r0), "=r"(r1), "=r"(r2), "=r"(r3) : "r"(addr));
}

__device__ __forceinline__ void mma_bf16(float* c, uint32_t a0, uint32_t a1, uint32_t a2,
                                         uint32_t a3, uint32_t b0, uint32_t b1) {
    asm volatile(
        "mma.sync.aligned.m16n8k16.row.col.f32.bf16.bf16.f32 "
        "{%0,%1,%2,%3}, {%4,%5,%6,%7}, {%8,%9}, {%0,%1,%2,%3};"
        : "+f"(c[0]), "+f"(c[1]), "+f"(c[2]), "+f"(c[3])
        : "r"(a0), "r"(a1), "r"(a2), "r"(a3), "r"(b0), "r"(b1));
}

__device__ __forceinline__ void cp16(uint32_t dst, const void* src) {
    asm volatile("cp.async.cg.shared.global [%0], [%1], 16;" :: "r"(dst), "l"(src));
}
#define CP_COMMIT() asm volatile("cp.async.commit_group;" ::: "memory")
#define CP_WAIT0()  asm volatile("cp.async.wait_group 0;" ::: "memory")

// ---------------- CSR build ----------------
__global__ void k_hist(const int* __restrict__ dst) {
    int e = blockIdx.x * blockDim.x + threadIdx.x;
    if (e < EE) atomicAdd(&g_deg[dst[e]], 1);
}

__global__ void k_offsets() {
    int i = blockIdx.x * blockDim.x + threadIdx.x;
    int lane = threadIdx.x & 31;
    int d = (i < NN) ? g_deg[i] : 0;
    int incl = d;
    #pragma unroll
    for (int off = 1; off < 32; off <<= 1) {
        int v = __shfl_up_sync(0xFFFFFFFFu, incl, off);
        if (lane >= off) incl += v;
    }
    int tot = __shfl_sync(0xFFFFFFFFu, incl, 31);
    int base = 0;
    if (lane == 31 && tot > 0) base = atomicAdd(&g_total, tot);
    base = __shfl_sync(0xFFFFFFFFu, base, 31);
    if (i < NN) {
        int excl = base + incl - d;
        g_rowstart[i] = excl;
        g_cursor[i]   = excl;
    }
}

__global__ void k_fill(const int* __restrict__ src, const int* __restrict__ dst) {
    int e = blockIdx.x * blockDim.x + threadIdx.x;
    if (e < EE) {
        int d = dst[e];
        int p = atomicAdd(&g_cursor[d], 1);
        g_col[p] = src[e] << 9;   // byte offset: src * 512
    }
}

// ---------------- W prep: bf16 split + swizzled [k][n] layout ----------------
__global__ void k_prep_w(const float* __restrict__ W1, const float* __restrict__ W2) {
    int idx = blockIdx.x;
    int layer = idx >> 1, which = idx & 1;
    const float* src = (which ? W2 : W1) + (size_t)layer * DD * DD;
    int t = threadIdx.x;
    int row = t >> 1, half = t & 1;    // row = k index

    char* dh = (char*)&g_wt[idx][0][0];
    char* dl = (char*)&g_wt[idx][1][0];
    const float4* s4 = (const float4*)(src + (size_t)row * 128 + half * 64);
    #pragma unroll
    for (int g = 0; g < 8; g++) {
        int cbase = half * 64 + g * 8;     // n index
        float4 u = __ldg(&s4[2 * g + 0]);
        float4 v = __ldg(&s4[2 * g + 1]);
        uint32_t h0, h1, h2, h3, l0, l1, l2, l3;
        split2(u.x, u.y, h0, l0);
        split2(u.z, u.w, h1, l1);
        split2(v.x, v.y, h2, l2);
        split2(v.z, v.w, h3, l3);
        uint32_t off = swz(row, cbase);
        *(uint4*)(dh + off) = make_uint4(h0, h1, h2, h3);
        *(uint4*)(dl + off) = make_uint4(l0, l1, l2, l3);
    }
}

// ---------------- aggregation: one warp per node, fp32 CSR gather ----------------
__global__ void k_aggregate(const float* __restrict__ X, int apply) {
    int warp = (blockIdx.x * blockDim.x + threadIdx.x) >> 5;
    int lane = threadIdx.x & 31;
    if (warp >= NN) return;
    const char* Hb = apply ? (const char*)g_bufA : (const char*)X;
    const char* Hl = Hb + (lane << 4);     // lane's 16B column slot

    float4 a4 = make_float4(1.f, 1.f, 1.f, 1.f);
    float4 s4 = make_float4(0.f, 0.f, 0.f, 0.f);
    if (apply) {
        a4 = *(const float4*)&g_scale2[lane * 4];
        s4 = *(const float4*)&g_shift2[lane * 4];
    }

    float4 v = __ldg((const float4*)(Hl + ((size_t)warp << 9)));
    float4 acc;
    if (apply) {
        acc.x = fmaxf(fmaf(v.x, a4.x, s4.x), 0.f);
        acc.y = fmaxf(fmaf(v.y, a4.y, s4.y), 0.f);
        acc.z = fmaxf(fmaf(v.z, a4.z, s4.z), 0.f);
        acc.w = fmaxf(fmaf(v.w, a4.w, s4.w), 0.f);
    } else {
        acc = v;
    }

    int s = g_rowstart[warp];
    int cnt = g_deg[warp];
    if (apply) {
        int j = 0;
        for (; j + 4 <= cnt; j += 4) {
            uint32_t s0 = (uint32_t)g_col[s + j + 0];
            uint32_t s1 = (uint32_t)g_col[s + j + 1];
            uint32_t s2 = (uint32_t)g_col[s + j + 2];
            uint32_t s3 = (uint32_t)g_col[s + j + 3];
            float4 v0 = __ldg((const float4*)(Hl + s0));
            float4 v1 = __ldg((const float4*)(Hl + s1));
            float4 v2 = __ldg((const float4*)(Hl + s2));
            float4 v3 = __ldg((const float4*)(Hl + s3));
            acc.x += fmaxf(fmaf(v0.x, a4.x, s4.x), 0.f) + fmaxf(fmaf(v1.x, a4.x, s4.x), 0.f)
                   + fmaxf(fmaf(v2.x, a4.x, s4.x), 0.f) + fmaxf(fmaf(v3.x, a4.x, s4.x), 0.f);
            acc.y += fmaxf(fmaf(v0.y, a4.y, s4.y), 0.f) + fmaxf(fmaf(v1.y, a4.y, s4.y), 0.f)
                   + fmaxf(fmaf(v2.y, a4.y, s4.y), 0.f) + fmaxf(fmaf(v3.y, a4.y, s4.y), 0.f);
            acc.z += fmaxf(fmaf(v0.z, a4.z, s4.z), 0.f) + fmaxf(fmaf(v1.z, a4.z, s4.z), 0.f)
                   + fmaxf(fmaf(v2.z, a4.z, s4.z), 0.f) + fmaxf(fmaf(v3.z, a4.z, s4.z), 0.f);
            acc.w += fmaxf(fmaf(v0.w, a4.w, s4.w), 0.f) + fmaxf(fmaf(v1.w, a4.w, s4.w), 0.f)
                   + fmaxf(fmaf(v2.w, a4.w, s4.w), 0.f) + fmaxf(fmaf(v3.w, a4.w, s4.w), 0.f);
        }
        for (; j < cnt; j++) {
            uint32_t s0 = (uint32_t)g_col[s + j];
            float4 v0 = __ldg((const float4*)(Hl + s0));
            acc.x += fmaxf(fmaf(v0.x, a4.x, s4.x), 0.f);
            acc.y += fmaxf(fmaf(v0.y, a4.y, s4.y), 0.f);
            acc.z += fmaxf(fmaf(v0.z, a4.z, s4.z), 0.f);
            acc.w += fmaxf(fmaf(v0.w, a4.w, s4.w), 0.f);
        }
    } else {
        int j = 0;
        for (; j + 4 <= cnt; j += 4) {
            uint32_t s0 = (uint32_t)g_col[s + j + 0];
            uint32_t s1 = (uint32_t)g_col[s + j + 1];
            uint32_t s2 = (uint32_t)g_col[s + j + 2];
            uint32_t s3 = (uint32_t)g_col[s + j + 3];
            float4 v0 = __ldg((const float4*)(Hl + s0));
            float4 v1 = __ldg((const float4*)(Hl + s1));
            float4 v2 = __ldg((const float4*)(Hl + s2));
            float4 v3 = __ldg((const float4*)(Hl + s3));
            acc.x += v0.x + v1.x + v2.x + v3.x;
            acc.y += v0.y + v1.y + v2.y + v3.y;
            acc.z += v0.z + v1.z + v2.z + v3.z;
            acc.w += v0.w + v1.w + v2.w + v3.w;
        }
        for (; j < cnt; j++) {
            uint32_t s0 = (uint32_t)g_col[s + j];
            float4 v0 = __ldg((const float4*)(Hl + s0));
            acc.x += v0.x; acc.y += v0.y; acc.z += v0.z; acc.w += v0.w;
        }
    }
    ((float4*)g_bufB)[(size_t)warp * 32 + lane] = acc;
}

// ---- persistent pipelined tensor-core GEMM (column-split pairs) + BN stats -----
// pair = blockIdx>>1 owns tiles {pair, pair+148, ...}; half = blockIdx&1 owns
// output cols [half*64, half*64+64). B-half resident; A staged via cp.async.
// which==0: A=g_bufB (no transform), C=g_bufC, writes scale1/shift1
// which==1: A=g_bufC with relu(scale1*v+shift1), C=g_bufA, writes scale2/shift2
__global__ __launch_bounds__(256, 2)
void k_gemm_mma(const float* __restrict__ bias, const float* __restrict__ gamma,
                const float* __restrict__ beta, int widx, int which) {
    extern __shared__ char smem[];
    uint32_t sb = smem_u32(smem);
    const float* __restrict__ A = which ? g_bufC : g_bufB;
    float* __restrict__ C       = which ? g_bufA : g_bufC;

    int t = threadIdx.x;
    int wid = t >> 5, lane = t & 31;
    int pair = blockIdx.x >> 1;
    int half = blockIdx.x & 1;
    int wm = (wid & 1) * 32;         // warp row offset (0 or 32)
    int wn = (wid >> 1) * 16;        // warp col offset within half (0..48)
    int quad = lane >> 2, tq = lane & 3;

    // --- B-half copy once: local chunk p <- gmem chunk (half*8 + p), 128B rows ---
    {
        const uint4* bh = &g_wt[widx][0][0];
        const uint4* bl = &g_wt[widx][1][0];
        uint4* sh4 = (uint4*)(smem + SM_BHI);
        uint4* sl4 = (uint4*)(smem + SM_BLO);
        int r = t >> 1, seg = t & 1;
        #pragma unroll
        for (int i = 0; i < 4; i++) {
            int li = r * 8 + seg * 4 + i;
            int gi = r * 16 + half * 8 + seg * 4 + i;
            sh4[li] = __ldg(&bh[gi]);
            sl4[li] = __ldg(&bl[gi]);
        }
    }

    // hoisted bias (global columns)
    float bx[2], by[2];
    #pragma unroll
    for (int nt = 0; nt < 2; nt++) {
        int cg = half * 64 + wn + nt * 8 + tq * 2;
        bx[nt] = __ldg(&bias[cg]);
        by[nt] = __ldg(&bias[cg + 1]);
    }

    // BN stat accumulators persist across tiles
    float cs[2][2], cq[2][2];
    #pragma unroll
    for (int nt = 0; nt < 2; nt++) {
        cs[nt][0] = 0.f; cs[nt][1] = 0.f;
        cq[nt][0] = 0.f; cq[nt][1] = 0.f;
    }

    int srow = t >> 2, sq = t & 3;   // stage row / quarter for this thread
    uint32_t stage_dst = sb + SM_STAGE + (uint32_t)(srow * STAGE_PITCH + sq * 128);

    // prefetch first tile
    if (pair < GEMM_TILES) {
        int gr = min(pair * 64 + srow, NN - 1);
        const char* srcp = (const char*)(A + (size_t)gr * 128) + sq * 128;
        #pragma unroll
        for (int i = 0; i < 8; i++) cp16(stage_dst + i * 16, srcp + i * 16);
        CP_COMMIT();
    }

    for (int tile = pair; tile < GEMM_TILES; tile += PAIRS) {
        int block_row = tile * 64;

        CP_WAIT0();
        __syncthreads();   // stage ready; previous mainloop fully done

        // --- A convert: stage fp32 -> split bf16, swizzled ---
        {
            const float4* sp = (const float4*)(smem + SM_STAGE + srow * STAGE_PITCH + sq * 128);
            #pragma unroll
            for (int g = 0; g < 4; g++) {
                int cbase = sq * 32 + g * 8;
                float4 u = sp[2 * g + 0];
                float4 v = sp[2 * g + 1];
                if (which) {
                    float4 sa  = *(const float4*)&g_scale1[cbase];
                    float4 sh4 = *(const float4*)&g_shift1[cbase];
                    float4 sa2 = *(const float4*)&g_scale1[cbase + 4];
                    float4 sh2 = *(const float4*)&g_shift1[cbase + 4];
                    u.x = fmaxf(fmaf(u.x, sa.x, sh4.x), 0.f);
                    u.y = fmaxf(fmaf(u.y, sa.y, sh4.y), 0.f);
                    u.z = fmaxf(fmaf(u.z, sa.z, sh4.z), 0.f);
                    u.w = fmaxf(fmaf(u.w, sa.w, sh4.w), 0.f);
                    v.x = fmaxf(fmaf(v.x, sa2.x, sh2.x), 0.f);
                    v.y = fmaxf(fmaf(v.y, sa2.y, sh2.y), 0.f);
                    v.z = fmaxf(fmaf(v.z, sa2.z, sh2.z), 0.f);
                    v.w = fmaxf(fmaf(v.w, sa2.w, sh2.w), 0.f);
                }
                uint32_t h0, h1, h2, h3, l0, l1, l2, l3;
                split2(u.x, u.y, h0, l0);
                split2(u.z, u.w, h1, l1);
                split2(v.x, v.y, h2, l2);
                split2(v.z, v.w, h3, l3);
                uint32_t off = swz(srow, cbase);
                *(uint4*)(smem + SM_AHI + off) = make_uint4(h0, h1, h2, h3);
                *(uint4*)(smem + SM_ALO + off) = make_uint4(l0, l1, l2, l3);
            }
        }
        __syncthreads();   // stage free; A tiles ready

        // prefetch next tile into stage (overlaps mainloop)
        int next = tile + PAIRS;
        if (next < GEMM_TILES) {
            int gr = min(next * 64 + srow, NN - 1);
            const char* srcp = (const char*)(A + (size_t)gr * 128) + sq * 128;
            #pragma unroll
            for (int i = 0; i < 8; i++) cp16(stage_dst + i * 16, srcp + i * 16);
            CP_COMMIT();
        }

        // --- MMA mainloop: warp tile 32x16 ---
        float acc[2][2][4];
        #pragma unroll
        for (int mt = 0; mt < 2; mt++)
            #pragma unroll
            for (int nt = 0; nt < 2; nt++)
                #pragma unroll
                for (int q = 0; q < 4; q++) acc[mt][nt][q] = 0.f;

        #pragma unroll
        for (int ks = 0; ks < 8; ks++) {
            uint32_t afh[2][4], afl[2][4];
            #pragma unroll
            for (int mt = 0; mt < 2; mt++) {
                int r = wm + mt * 16 + (lane & 15);
                int chunk = ks * 2 + (lane >> 4);
                uint32_t off = (uint32_t)(r * 256 + ((chunk ^ (r & 7)) << 4));
                ldsm_x4(sb + SM_AHI + off, afh[mt][0], afh[mt][1], afh[mt][2], afh[mt][3]);
                ldsm_x4(sb + SM_ALO + off, afl[mt][0], afl[mt][1], afl[mt][2], afl[mt][3]);
            }
            // B-half: 128B row pitch, 8 chunks/row
            uint32_t bfh[2][2], bfl[2][2];
            {
                int r = ks * 16 + (lane & 15);
                int chunk = (wn >> 3) + (lane >> 4);
                uint32_t off = (uint32_t)(r * 128 + ((chunk ^ (r & 7)) << 4));
                uint32_t b0, b1, b2, b3;
                ldsm_x4_t(sb + SM_BHI + off, b0, b1, b2, b3);
                bfh[0][0] = b0; bfh[0][1] = b1;
                bfh[1][0] = b2; bfh[1][1] = b3;
                ldsm_x4_t(sb + SM_BLO + off, b0, b1, b2, b3);
                bfl[0][0] = b0; bfl[0][1] = b1;
                bfl[1][0] = b2; bfl[1][1] = b3;
            }
            #pragma unroll
            for (int mt = 0; mt < 2; mt++)
                #pragma unroll
                for (int nt = 0; nt < 2; nt++) {
                    mma_bf16(acc[mt][nt], afh[mt][0], afh[mt][1], afh[mt][2], afh[mt][3],
                             bfh[nt][0], bfh[nt][1]);
                    mma_bf16(acc[mt][nt], afh[mt][0], afh[mt][1], afh[mt][2], afh[mt][3],
                             bfl[nt][0], bfl[nt][1]);
                    mma_bf16(acc[mt][nt], afl[mt][0], afl[mt][1], afl[mt][2], afl[mt][3],
                             bfh[nt][0], bfh[nt][1]);
                }
        }

        // --- per-tile epilogue: bias add + store + accumulate stats in regs ---
        #pragma unroll
        for (int mt = 0; mt < 2; mt++) {
            int r0 = block_row + wm + mt * 16 + quad;
            bool ok0 = (r0 < NN), ok1 = (r0 + 8 < NN);
            #pragma unroll
            for (int nt = 0; nt < 2; nt++) {
                int cg = half * 64 + wn + nt * 8 + tq * 2;
                float o0 = acc[mt][nt][0] + bx[nt];
                float o1 = acc[mt][nt][1] + by[nt];
                float o2 = acc[mt][nt][2] + bx[nt];
                float o3 = acc[mt][nt][3] + by[nt];
                if (ok0) {
                    *(float2*)(C + (size_t)r0 * 128 + cg) = make_float2(o0, o1);
                    cs[nt][0] += o0; cq[nt][0] += o0 * o0;
                    cs[nt][1] += o1; cq[nt][1] += o1 * o1;
                }
                if (ok1) {
                    *(float2*)(C + (size_t)(r0 + 8) * 128 + cg) = make_float2(o2, o3);
                    cs[nt][0] += o2; cq[nt][0] += o2 * o2;
                    cs[nt][1] += o3; cq[nt][1] += o3 * o3;
                }
            }
        }
    }

    // --- once per CTA: reduce stats and finalize ---
    #pragma unroll
    for (int nt = 0; nt < 2; nt++) {
        #pragma unroll
        for (int h = 0; h < 2; h++) {
            float s = cs[nt][h], q = cq[nt][h];
            s += __shfl_xor_sync(0xFFFFFFFFu, s, 16);
            q += __shfl_xor_sync(0xFFFFFFFFu, q, 16);
            s += __shfl_xor_sync(0xFFFFFFFFu, s, 8);
            q += __shfl_xor_sync(0xFFFFFFFFu, q, 8);
            s += __shfl_xor_sync(0xFFFFFFFFu, s, 4);
            q += __shfl_xor_sync(0xFFFFFFFFu, q, 4);
            cs[nt][h] = s; cq[nt][h] = q;
        }
    }

    __syncthreads();
    float* s_s = (float*)smem;             // [2][64]: rowgroup x local column
    float* s_q = (float*)(smem + 512);
    if (quad == 0) {
        int rg = wid & 1;
        #pragma unroll
        for (int nt = 0; nt < 2; nt++) {
            int cl = wn + nt * 8 + tq * 2;
            s_s[rg * 64 + cl]     = cs[nt][0];
            s_s[rg * 64 + cl + 1] = cs[nt][1];
            s_q[rg * 64 + cl]     = cq[nt][0];
            s_q[rg * 64 + cl + 1] = cq[nt][1];
        }
    }
    __syncthreads();
    if (t < 64) {
        float s = s_s[t] + s_s[64 + t];
        float q = s_q[t] + s_q[64 + t];
        atomicAdd(&g_acc_s[half * 64 + t], s);
        atomicAdd(&g_acc_q[half * 64 + t], q);
    }
    __threadfence();
    __syncthreads();

    // --- last-CTA BN finalize ---
    __shared__ int s_last;
    if (t == 0) s_last = (atomicAdd(&g_done, 1) == PERSIST_GRID - 1) ? 1 : 0;
    __syncthreads();
    if (s_last) {
        __threadfence();
        if (t < 128) {
            float s = g_acc_s[t];
            float q = g_acc_q[t];
            float inv_n = 1.f / (float)NN;
            float mean = s * inv_n;
            float var  = q * inv_n - mean * mean;
            float a  = gamma[t] * rsqrtf(var + BN_EPS);
            float sh = beta[t] - mean * a;
            if (which) { g_scale2[t] = a; g_shift2[t] = sh; }
            else       { g_scale1[t] = a; g_shift1[t] = sh; }
            g_acc_s[t] = 0.f;
            g_acc_q[t] = 0.f;
        }
        if (t == 0) g_done = 0;
    }
}

// ---------------- global add pool (batch sorted -> run-length accumulate) -------
__global__ void k_pool(const int* __restrict__ batch, float* __restrict__ out) {
    int c = threadIdx.x & 127;
    int half = threadIdx.x >> 7;
    int r0 = blockIdx.x * 64;
    int rend = min(r0 + 64, NN);
    float a = g_scale2[c];
    float s2 = g_shift2[c];
    int cur = -1;
    float acc = 0.f;
    for (int r = r0 + half; r < rend; r += 2) {
        int b = batch[r];
        if (b != cur) {
            if (cur >= 0) atomicAdd(&out[(size_t)cur * 128 + c], acc);
            cur = b;
            acc = 0.f;
        }
        float v = g_bufA[(size_t)r * 128 + c];
        acc += fmaxf(fmaf(v, a, s2), 0.f);
    }
    if (cur >= 0) atomicAdd(&out[(size_t)cur * 128 + c], acc);
}

// ---------------- launch ----------------
extern "C" void kernel_launch(void* const* d_in, const int* in_sizes, int n_in,
                              void* d_out, int out_size) {
    const float* x      = (const float*)d_in[0];
    const int*   eidx   = (const int*)d_in[1];
    const int*   batch  = (const int*)d_in[2];
    const float* W1     = (const float*)d_in[3];
    const float* b1     = (const float*)d_in[4];
    const float* g1     = (const float*)d_in[5];
    const float* be1    = (const float*)d_in[6];
    const float* W2     = (const float*)d_in[7];
    const float* b2     = (const float*)d_in[8];
    const float* g2     = (const float*)d_in[9];
    const float* be2    = (const float*)d_in[10];
    float* out = (float*)d_out;

    const int* src = eidx;
    const int* dst = eidx + EE;

    cudaFuncSetAttribute(k_gemm_mma, cudaFuncAttributeMaxDynamicSharedMemorySize, SMEM_TOT);

    const int agg_grid = (NN + 7) / 8;   // 6250 (8 warps/block)

    // zero g_deg / g_total via memset
    void *p_deg = nullptr, *p_total = nullptr;
    cudaGetSymbolAddress(&p_deg, g_deg);
    cudaGetSymbolAddress(&p_total, g_total);
    cudaMemsetAsync(p_deg, 0, NN * sizeof(int));
    cudaMemsetAsync(p_total, 0, sizeof(int));

    // --- CSR build (reused for all 3 layers) ---
    k_hist<<<(EE + 255) / 256, 256>>>(dst);
    k_offsets<<<(NN + 255) / 256, 256>>>();
    k_fill<<<(EE + 255) / 256, 256>>>(src, dst);

    for (int i = 0; i < LL; i++) {
        k_aggregate<<<agg_grid, 256>>>(x, i > 0 ? 1 : 0);
        if (i == 0) k_prep_w<<<6, 256>>>(W1, W2);
        k_gemm_mma<<<PERSIST_GRID, 256, SMEM_TOT>>>(b1 + i * DD, g1 + i * DD, be1 + i * DD,
                                                    i * 2 + 0, 0);
        k_gemm_mma<<<PERSIST_GRID, 256, SMEM_TOT>>>(b2 + i * DD, g2 + i * DD, be2 + i * DD,
                                                    i * 2 + 1, 1);
    }

    cudaMemsetAsync(out, 0, (size_t)BB * DD * sizeof(float));
    k_pool<<<(NN + 63) / 64, 256>>>(batch, out);
}

// round 17
// speedup vs baseline: 1.2440x; 1.2440x over previous
#include <cuda_runtime.h>
#include <cuda_bf16.h>
#include <cstdint>

// Problem constants
#define NN 50000
#define EE 800000
#define DD 128
#define LL 3
#define BB 256
#define BN_EPS 1e-5f
#define GEMM_TILES ((NN + 63) / 64)    // 782 BM=64 tiles
#define PERSIST_GRID 296               // 2 CTAs/SM x 148 SMs

// smem layout for tensor GEMM (bf16 tiles, 256B row pitch, xor-swizzled chunks)
// A tile: 64 rows (16KB per hi/lo); B tile: 128 rows (32KB per hi/lo). Total 96KB.
#define SM_AHI 0
#define SM_ALO 16384
#define SM_BHI 32768
#define SM_BLO 65536
#define SMEM_TOT 98304

// ---------------- scratch (static device globals; no allocation) ----------------
__device__ float g_bufA[(size_t)NN * DD];   // z: raw pre-BN2 layer output
__device__ float g_bufB[(size_t)NN * DD];   // agg (input to GEMM1)
__device__ float g_bufC[(size_t)NN * DD];   // y: raw pre-BN1 hidden
__device__ int   g_deg[NN];
__device__ int   g_rowstart[NN];
__device__ int   g_cursor[NN];
__device__ int   g_col[EE];                 // BYTE offsets (src*512)
__device__ int   g_total;
__device__ float g_acc_s[DD];               // BN stat accumulators (zero-init; self-reset)
__device__ float g_acc_q[DD];
__device__ int   g_done;                    // last-CTA counter (zero-init; self-reset)
__device__ float g_scale1[DD];
__device__ float g_shift1[DD];
__device__ float g_scale2[DD];
__device__ float g_shift2[DD];
// prepared weights: [layer*2+which][hi/lo][32KB tile as uint4], swizzled [k][n] layout
__device__ uint4 g_wt[6][2][2048];

// ---------------- helpers ----------------
__device__ __forceinline__ uint32_t smem_u32(const void* p) {
    uint32_t a;
    asm("{ .reg .u64 t; cvta.to.shared.u64 t, %1; cvt.u32.u64 %0, t; }" : "=r"(a) : "l"(p));
    return a;
}

// byte offset inside a [rows]x128 bf16 tile (256B rows, 16B chunks, xor swizzle)
__device__ __forceinline__ uint32_t swz(int row, int col8) {
    int chunk = col8 >> 3;
    return (uint32_t)(row * 256 + ((chunk ^ (row & 7)) << 4));
}

// split fp32 pair -> bf16x2 hi + bf16x2 lo
__device__ __forceinline__ void split2(float a, float b, uint32_t& hi, uint32_t& lo) {
    __nv_bfloat162 h = __floats2bfloat162_rn(a, b);
    uint32_t uh = *reinterpret_cast<uint32_t*>(&h);
    float ra = __uint_as_float((uh & 0xFFFFu) << 16);
    float rb = __uint_as_float(uh & 0xFFFF0000u);
    __nv_bfloat162 l = __floats2bfloat162_rn(a - ra, b - rb);
    hi = uh;
    lo = *reinterpret_cast<uint32_t*>(&l);
}

__device__ __forceinline__ void ldsm_x4(uint32_t addr, uint32_t& r0, uint32_t& r1,
                                        uint32_t& r2, uint32_t& r3) {
    asm volatile("ldmatrix.sync.aligned.m8n8.x4.shared.b16 {%0,%1,%2,%3}, [%4];"
                 : "=r"(r0), "=r"(r1), "=r"(r2), "=r"(r3) : "r"(addr));
}

__device__ __forceinline__ void ldsm_x4_t(uint32_t addr, uint32_t& r0, uint32_t& r1,
                                          uint32_t& r2, uint32_t& r3) {
    asm volatile("ldmatrix.sync.aligned.m8n8.x4.trans.shared.b16 {%0,%1,%2,%3}, [%4];"
                 : "=r"(r0), "=r"(r1), "=r"(r2), "=r"(r3) : "r"(addr));
}

__device__ __forceinline__ void mma_bf16(float* c, uint32_t a0, uint32_t a1, uint32_t a2,
                                         uint32_t a3, uint32_t b0, uint32_t b1) {
    asm volatile(
        "mma.sync.aligned.m16n8k16.row.col.f32.bf16.bf16.f32 "
        "{%0,%1,%2,%3}, {%4,%5,%6,%7}, {%8,%9}, {%0,%1,%2,%3};"
        : "+f"(c[0]), "+f"(c[1]), "+f"(c[2]), "+f"(c[3])
        : "r"(a0), "r"(a1), "r"(a2), "r"(a3), "r"(b0), "r"(b1));
}

// ---------------- CSR build ----------------
__global__ void k_hist(const int* __restrict__ dst) {
    int e = blockIdx.x * blockDim.x + threadIdx.x;
    if (e < EE) atomicAdd(&g_deg[dst[e]], 1);
}

// warp-aggregated exclusive offsets (segment order nondeterministic; sums unaffected)
__global__ void k_offsets() {
    int i = blockIdx.x * blockDim.x + threadIdx.x;
    int lane = threadIdx.x & 31;
    int d = (i < NN) ? g_deg[i] : 0;
    int incl = d;
    #pragma unroll
    for (int off = 1; off < 32; off <<= 1) {
        int v = __shfl_up_sync(0xFFFFFFFFu, incl, off);
        if (lane >= off) incl += v;
    }
    int tot = __shfl_sync(0xFFFFFFFFu, incl, 31);
    int base = 0;
    if (lane == 31 && tot > 0) base = atomicAdd(&g_total, tot);
    base = __shfl_sync(0xFFFFFFFFu, base, 31);
    if (i < NN) {
        int excl = base + incl - d;
        g_rowstart[i] = excl;
        g_cursor[i]   = excl;
    }
}

__global__ void k_fill(const int* __restrict__ src, const int* __restrict__ dst) {
    int e = blockIdx.x * blockDim.x + threadIdx.x;
    if (e < EE) {
        int d = dst[e];
        int p = atomicAdd(&g_cursor[d], 1);
        g_col[p] = src[e] << 9;   // byte offset: src * 512
    }
}

// ---------------- W prep: bf16 split + swizzled [k][n] layout ----------------
__global__ void k_prep_w(const float* __restrict__ W1, const float* __restrict__ W2) {
    int idx = blockIdx.x;
    int layer = idx >> 1, which = idx & 1;
    const float* src = (which ? W2 : W1) + (size_t)layer * DD * DD;
    int t = threadIdx.x;
    int row = t >> 1, half = t & 1;    // row = k index

    char* dh = (char*)&g_wt[idx][0][0];
    char* dl = (char*)&g_wt[idx][1][0];
    const float4* s4 = (const float4*)(src + (size_t)row * 128 + half * 64);
    #pragma unroll
    for (int g = 0; g < 8; g++) {
        int cbase = half * 64 + g * 8;     // n index
        float4 u = __ldg(&s4[2 * g + 0]);
        float4 v = __ldg(&s4[2 * g + 1]);
        uint32_t h0, h1, h2, h3, l0, l1, l2, l3;
        split2(u.x, u.y, h0, l0);
        split2(u.z, u.w, h1, l1);
        split2(v.x, v.y, h2, l2);
        split2(v.z, v.w, h3, l3);
        uint32_t off = swz(row, cbase);
        *(uint4*)(dh + off) = make_uint4(h0, h1, h2, h3);
        *(uint4*)(dl + off) = make_uint4(l0, l1, l2, l3);
    }
}

// ---------------- aggregation: one warp per node, fp32 CSR gather ----------------
__global__ void k_aggregate(const float* __restrict__ X, int apply) {
    int warp = (blockIdx.x * blockDim.x + threadIdx.x) >> 5;
    int lane = threadIdx.x & 31;
    if (warp >= NN) return;
    const char* Hb = apply ? (const char*)g_bufA : (const char*)X;
    const char* Hl = Hb + (lane << 4);     // lane's 16B column slot

    float4 a4 = make_float4(1.f, 1.f, 1.f, 1.f);
    float4 s4 = make_float4(0.f, 0.f, 0.f, 0.f);
    if (apply) {
        a4 = *(const float4*)&g_scale2[lane * 4];
        s4 = *(const float4*)&g_shift2[lane * 4];
    }

    float4 v = __ldg((const float4*)(Hl + ((size_t)warp << 9)));
    float4 acc;
    if (apply) {
        acc.x = fmaxf(fmaf(v.x, a4.x, s4.x), 0.f);
        acc.y = fmaxf(fmaf(v.y, a4.y, s4.y), 0.f);
        acc.z = fmaxf(fmaf(v.z, a4.z, s4.z), 0.f);
        acc.w = fmaxf(fmaf(v.w, a4.w, s4.w), 0.f);
    } else {
        acc = v;
    }

    int s = g_rowstart[warp];
    int cnt = g_deg[warp];
    if (apply) {
        int j = 0;
        for (; j + 4 <= cnt; j += 4) {
            uint32_t s0 = (uint32_t)g_col[s + j + 0];
            uint32_t s1 = (uint32_t)g_col[s + j + 1];
            uint32_t s2 = (uint32_t)g_col[s + j + 2];
            uint32_t s3 = (uint32_t)g_col[s + j + 3];
            float4 v0 = __ldg((const float4*)(Hl + s0));
            float4 v1 = __ldg((const float4*)(Hl + s1));
            float4 v2 = __ldg((const float4*)(Hl + s2));
            float4 v3 = __ldg((const float4*)(Hl + s3));
            acc.x += fmaxf(fmaf(v0.x, a4.x, s4.x), 0.f) + fmaxf(fmaf(v1.x, a4.x, s4.x), 0.f)
                   + fmaxf(fmaf(v2.x, a4.x, s4.x), 0.f) + fmaxf(fmaf(v3.x, a4.x, s4.x), 0.f);
            acc.y += fmaxf(fmaf(v0.y, a4.y, s4.y), 0.f) + fmaxf(fmaf(v1.y, a4.y, s4.y), 0.f)
                   + fmaxf(fmaf(v2.y, a4.y, s4.y), 0.f) + fmaxf(fmaf(v3.y, a4.y, s4.y), 0.f);
            acc.z += fmaxf(fmaf(v0.z, a4.z, s4.z), 0.f) + fmaxf(fmaf(v1.z, a4.z, s4.z), 0.f)
                   + fmaxf(fmaf(v2.z, a4.z, s4.z), 0.f) + fmaxf(fmaf(v3.z, a4.z, s4.z), 0.f);
            acc.w += fmaxf(fmaf(v0.w, a4.w, s4.w), 0.f) + fmaxf(fmaf(v1.w, a4.w, s4.w), 0.f)
                   + fmaxf(fmaf(v2.w, a4.w, s4.w), 0.f) + fmaxf(fmaf(v3.w, a4.w, s4.w), 0.f);
        }
        for (; j < cnt; j++) {
            uint32_t s0 = (uint32_t)g_col[s + j];
            float4 v0 = __ldg((const float4*)(Hl + s0));
            acc.x += fmaxf(fmaf(v0.x, a4.x, s4.x), 0.f);
            acc.y += fmaxf(fmaf(v0.y, a4.y, s4.y), 0.f);
            acc.z += fmaxf(fmaf(v0.z, a4.z, s4.z), 0.f);
            acc.w += fmaxf(fmaf(v0.w, a4.w, s4.w), 0.f);
        }
    } else {
        int j = 0;
        for (; j + 4 <= cnt; j += 4) {
            uint32_t s0 = (uint32_t)g_col[s + j + 0];
            uint32_t s1 = (uint32_t)g_col[s + j + 1];
            uint32_t s2 = (uint32_t)g_col[s + j + 2];
            uint32_t s3 = (uint32_t)g_col[s + j + 3];
            float4 v0 = __ldg((const float4*)(Hl + s0));
            float4 v1 = __ldg((const float4*)(Hl + s1));
            float4 v2 = __ldg((const float4*)(Hl + s2));
            float4 v3 = __ldg((const float4*)(Hl + s3));
            acc.x += v0.x + v1.x + v2.x + v3.x;
            acc.y += v0.y + v1.y + v2.y + v3.y;
            acc.z += v0.z + v1.z + v2.z + v3.z;
            acc.w += v0.w + v1.w + v2.w + v3.w;
        }
        for (; j < cnt; j++) {
            uint32_t s0 = (uint32_t)g_col[s + j];
            float4 v0 = __ldg((const float4*)(Hl + s0));
            acc.x += v0.x; acc.y += v0.y; acc.z += v0.z; acc.w += v0.w;
        }
    }
    ((float4*)g_bufB)[(size_t)warp * 32 + lane] = acc;
}

// ---------------- persistent tensor-core GEMM + fused BN stats + finalize -------
// grid = PERSIST_GRID (2 CTAs/SM); each CTA loops over tiles (BM=64), B resident.
// which==0: A=g_bufB (no transform), C=g_bufC, writes scale1/shift1
// which==1: A=g_bufC with relu(scale1*v+shift1), C=g_bufA, writes scale2/shift2
__global__ __launch_bounds__(256, 2)
void k_gemm_mma(const float* __restrict__ bias, const float* __restrict__ gamma,
                const float* __restrict__ beta, int widx, int which) {
    extern __shared__ char smem[];
    uint32_t sb = smem_u32(smem);
    const float* __restrict__ A = which ? g_bufC : g_bufB;
    float* __restrict__ C       = which ? g_bufA : g_bufC;

    int t = threadIdx.x;
    int wid = t >> 5, lane = t & 31;
    int wm = (wid & 1) * 32;     // warp row offset (0 or 32)
    int wn = (wid >> 1) * 32;    // warp col offset (0..96)
    int quad = lane >> 2, tq = lane & 3;

    // --- B copy once (pre-swizzled bytes, full 128x128 tile) ---
    {
        const uint4* bh = &g_wt[widx][0][0];
        const uint4* bl = &g_wt[widx][1][0];
        uint4* sh4 = (uint4*)(smem + SM_BHI);
        uint4* sl4 = (uint4*)(smem + SM_BLO);
        #pragma unroll
        for (int i = 0; i < 8; i++) {
            sh4[t + 256 * i] = __ldg(&bh[t + 256 * i]);
            sl4[t + 256 * i] = __ldg(&bl[t + 256 * i]);
        }
    }

    // hoisted bias per (nt) column pair
    float bx[4], by[4];
    #pragma unroll
    for (int nt = 0; nt < 4; nt++) {
        int c = wn + nt * 8 + tq * 2;
        bx[nt] = __ldg(&bias[c]);
        by[nt] = __ldg(&bias[c + 1]);
    }

    // BN stat accumulators persist across tiles
    float cs[4][2], cq[4][2];
    #pragma unroll
    for (int nt = 0; nt < 4; nt++) {
        cs[nt][0] = 0.f; cs[nt][1] = 0.f;
        cq[nt][0] = 0.f; cq[nt][1] = 0.f;
    }

    for (int tile = blockIdx.x; tile < GEMM_TILES; tile += PERSIST_GRID) {
        int block_row = tile * 64;

        __syncthreads();   // protect A smem from previous mainloop; covers B for iter 0

        // --- A convert: fp32 -> split bf16, swizzled (4 threads per row, 64 rows) ---
        {
            int row = t >> 2, quarter = t & 3;
            int gr = block_row + row;
            bool ok = (gr < NN);
            const float4* a4 = (const float4*)(A + (size_t)gr * 128 + quarter * 32);
            #pragma unroll
            for (int g = 0; g < 4; g++) {
                int cbase = quarter * 32 + g * 8;
                float4 u = ok ? __ldg(&a4[2 * g + 0]) : make_float4(0.f, 0.f, 0.f, 0.f);
                float4 v = ok ? __ldg(&a4[2 * g + 1]) : make_float4(0.f, 0.f, 0.f, 0.f);
                if (which) {
                    float4 sa  = *(const float4*)&g_scale1[cbase];
                    float4 sh4 = *(const float4*)&g_shift1[cbase];
                    float4 sa2 = *(const float4*)&g_scale1[cbase + 4];
                    float4 sh2 = *(const float4*)&g_shift1[cbase + 4];
                    u.x = fmaxf(fmaf(u.x, sa.x, sh4.x), 0.f);
                    u.y = fmaxf(fmaf(u.y, sa.y, sh4.y), 0.f);
                    u.z = fmaxf(fmaf(u.z, sa.z, sh4.z), 0.f);
                    u.w = fmaxf(fmaf(u.w, sa.w, sh4.w), 0.f);
                    v.x = fmaxf(fmaf(v.x, sa2.x, sh2.x), 0.f);
                    v.y = fmaxf(fmaf(v.y, sa2.y, sh2.y), 0.f);
                    v.z = fmaxf(fmaf(v.z, sa2.z, sh2.z), 0.f);
                    v.w = fmaxf(fmaf(v.w, sa2.w, sh2.w), 0.f);
                }
                uint32_t h0, h1, h2, h3, l0, l1, l2, l3;
                split2(u.x, u.y, h0, l0);
                split2(u.z, u.w, h1, l1);
                split2(v.x, v.y, h2, l2);
                split2(v.z, v.w, h3, l3);
                uint32_t off = swz(row, cbase);
                *(uint4*)(smem + SM_AHI + off) = make_uint4(h0, h1, h2, h3);
                *(uint4*)(smem + SM_ALO + off) = make_uint4(l0, l1, l2, l3);
            }
        }
        __syncthreads();

        // --- MMA mainloop: warp tile 32x32 (2x4 warp grid) ---
        float acc[2][4][4];
        #pragma unroll
        for (int mt = 0; mt < 2; mt++)
            #pragma unroll
            for (int nt = 0; nt < 4; nt++)
                #pragma unroll
                for (int q = 0; q < 4; q++) acc[mt][nt][q] = 0.f;

        #pragma unroll
        for (int ks = 0; ks < 8; ks++) {
            uint32_t afh[2][4], afl[2][4];
            #pragma unroll
            for (int mt = 0; mt < 2; mt++) {
                int r = wm + mt * 16 + (lane & 15);
                int chunk = ks * 2 + (lane >> 4);
                uint32_t off = (uint32_t)(r * 256 + ((chunk ^ (r & 7)) << 4));
                ldsm_x4(sb + SM_AHI + off, afh[mt][0], afh[mt][1], afh[mt][2], afh[mt][3]);
                ldsm_x4(sb + SM_ALO + off, afl[mt][0], afl[mt][1], afl[mt][2], afl[mt][3]);
            }
            uint32_t bfh[4][2], bfl[4][2];
            #pragma unroll
            for (int np = 0; np < 2; np++) {
                int r = ks * 16 + (lane & 15);
                int chunk = ((wn + np * 16) >> 3) + (lane >> 4);
                uint32_t off = (uint32_t)(r * 256 + ((chunk ^ (r & 7)) << 4));
                uint32_t b0, b1, b2, b3;
                ldsm_x4_t(sb + SM_BHI + off, b0, b1, b2, b3);
                bfh[np * 2 + 0][0] = b0; bfh[np * 2 + 0][1] = b1;
                bfh[np * 2 + 1][0] = b2; bfh[np * 2 + 1][1] = b3;
                ldsm_x4_t(sb + SM_BLO + off, b0, b1, b2, b3);
                bfl[np * 2 + 0][0] = b0; bfl[np * 2 + 0][1] = b1;
                bfl[np * 2 + 1][0] = b2; bfl[np * 2 + 1][1] = b3;
            }
            #pragma unroll
            for (int mt = 0; mt < 2; mt++)
                #pragma unroll
                for (int nt = 0; nt < 4; nt++) {
                    mma_bf16(acc[mt][nt], afh[mt][0], afh[mt][1], afh[mt][2], afh[mt][3],
                             bfh[nt][0], bfh[nt][1]);
                    mma_bf16(acc[mt][nt], afh[mt][0], afh[mt][1], afh[mt][2], afh[mt][3],
                             bfl[nt][0], bfl[nt][1]);
                    mma_bf16(acc[mt][nt], afl[mt][0], afl[mt][1], afl[mt][2], afl[mt][3],
                             bfh[nt][0], bfh[nt][1]);
                }
        }

        // --- per-tile epilogue: bias add + store + accumulate stats in regs ---
        #pragma unroll
        for (int mt = 0; mt < 2; mt++) {
            int r0 = block_row + wm + mt * 16 + quad;
            bool ok0 = (r0 < NN), ok1 = (r0 + 8 < NN);
            #pragma unroll
            for (int nt = 0; nt < 4; nt++) {
                int c = wn + nt * 8 + tq * 2;
                float o0 = acc[mt][nt][0] + bx[nt];
                float o1 = acc[mt][nt][1] + by[nt];
                float o2 = acc[mt][nt][2] + bx[nt];
                float o3 = acc[mt][nt][3] + by[nt];
                if (ok0) {
                    *(float2*)(C + (size_t)r0 * 128 + c) = make_float2(o0, o1);
                    cs[nt][0] += o0; cq[nt][0] += o0 * o0;
                    cs[nt][1] += o1; cq[nt][1] += o1 * o1;
                }
                if (ok1) {
                    *(float2*)(C + (size_t)(r0 + 8) * 128 + c) = make_float2(o2, o3);
                    cs[nt][0] += o2; cq[nt][0] += o2 * o2;
                    cs[nt][1] += o3; cq[nt][1] += o3 * o3;
                }
            }
        }
    }

    // --- once per CTA: reduce stats and finalize ---
    #pragma unroll
    for (int nt = 0; nt < 4; nt++) {
        #pragma unroll
        for (int h = 0; h < 2; h++) {
            float s = cs[nt][h], q = cq[nt][h];
            s += __shfl_xor_sync(0xFFFFFFFFu, s, 16);
            q += __shfl_xor_sync(0xFFFFFFFFu, q, 16);
            s += __shfl_xor_sync(0xFFFFFFFFu, s, 8);
            q += __shfl_xor_sync(0xFFFFFFFFu, q, 8);
            s += __shfl_xor_sync(0xFFFFFFFFu, s, 4);
            q += __shfl_xor_sync(0xFFFFFFFFu, q, 4);
            cs[nt][h] = s; cq[nt][h] = q;
        }
    }

    __syncthreads();
    float* s_s = (float*)smem;             // [2][128]: rowgroup x column
    float* s_q = (float*)(smem + 1024);
    if (quad == 0) {
        int rg = wid & 1;
        #pragma unroll
        for (int nt = 0; nt < 4; nt++) {
            int c = wn + nt * 8 + tq * 2;
            s_s[rg * 128 + c]     = cs[nt][0];
            s_s[rg * 128 + c + 1] = cs[nt][1];
            s_q[rg * 128 + c]     = cq[nt][0];
            s_q[rg * 128 + c + 1] = cq[nt][1];
        }
    }
    __syncthreads();
    if (t < 128) {
        float s = s_s[t] + s_s[128 + t];
        float q = s_q[t] + s_q[128 + t];
        atomicAdd(&g_acc_s[t], s);
        atomicAdd(&g_acc_q[t], q);
    }
    __threadfence();
    __syncthreads();

    // --- last-CTA BN finalize ---
    __shared__ int s_last;
    if (t == 0) s_last = (atomicAdd(&g_done, 1) == PERSIST_GRID - 1) ? 1 : 0;
    __syncthreads();
    if (s_last) {
        __threadfence();
        if (t < 128) {
            float s = g_acc_s[t];
            float q = g_acc_q[t];
            float inv_n = 1.f / (float)NN;
            float mean = s * inv_n;
            float var  = q * inv_n - mean * mean;
            float a  = gamma[t] * rsqrtf(var + BN_EPS);
            float sh = beta[t] - mean * a;
            if (which) { g_scale2[t] = a; g_shift2[t] = sh; }
            else       { g_scale1[t] = a; g_shift1[t] = sh; }
            g_acc_s[t] = 0.f;
            g_acc_q[t] = 0.f;
        }
        if (t == 0) g_done = 0;
    }
}

// ---------------- global add pool (batch sorted -> run-length accumulate) -------
__global__ void k_pool(const int* __restrict__ batch, float* __restrict__ out) {
    int c = threadIdx.x & 127;
    int half = threadIdx.x >> 7;
    int r0 = blockIdx.x * 64;
    int rend = min(r0 + 64, NN);
    float a = g_scale2[c];
    float s2 = g_shift2[c];
    int cur = -1;
    float acc = 0.f;
    for (int r = r0 + half; r < rend; r += 2) {
        int b = batch[r];
        if (b != cur) {
            if (cur >= 0) atomicAdd(&out[(size_t)cur * 128 + c], acc);
            cur = b;
            acc = 0.f;
        }
        float v = g_bufA[(size_t)r * 128 + c];
        acc += fmaxf(fmaf(v, a, s2), 0.f);
    }
    if (cur >= 0) atomicAdd(&out[(size_t)cur * 128 + c], acc);
}

// ---------------- launch ----------------
extern "C" void kernel_launch(void* const* d_in, const int* in_sizes, int n_in,
                              void* d_out, int out_size) {
    const float* x      = (const float*)d_in[0];
    const int*   eidx   = (const int*)d_in[1];
    const int*   batch  = (const int*)d_in[2];
    const float* W1     = (const float*)d_in[3];
    const float* b1     = (const float*)d_in[4];
    const float* g1     = (const float*)d_in[5];
    const float* be1    = (const float*)d_in[6];
    const float* W2     = (const float*)d_in[7];
    const float* b2     = (const float*)d_in[8];
    const float* g2     = (const float*)d_in[9];
    const float* be2    = (const float*)d_in[10];
    float* out = (float*)d_out;

    const int* src = eidx;
    const int* dst = eidx + EE;

    cudaFuncSetAttribute(k_gemm_mma, cudaFuncAttributeMaxDynamicSharedMemorySize, SMEM_TOT);

    const int agg_grid = (NN + 7) / 8;   // 6250 (8 warps/block)

    // zero g_deg / g_total via memset
    void *p_deg = nullptr, *p_total = nullptr;
    cudaGetSymbolAddress(&p_deg, g_deg);
    cudaGetSymbolAddress(&p_total, g_total);
    cudaMemsetAsync(p_deg, 0, NN * sizeof(int));
    cudaMemsetAsync(p_total, 0, sizeof(int));

    // --- CSR build (reused for all 3 layers) ---
    k_hist<<<(EE + 255) / 256, 256>>>(dst);
    k_offsets<<<(NN + 255) / 256, 256>>>();
    k_fill<<<(EE + 255) / 256, 256>>>(src, dst);

    for (int i = 0; i < LL; i++) {
        k_aggregate<<<agg_grid, 256>>>(x, i > 0 ? 1 : 0);
        if (i == 0) k_prep_w<<<6, 256>>>(W1, W2);
        k_gemm_mma<<<PERSIST_GRID, 256, SMEM_TOT>>>(b1 + i * DD, g1 + i * DD, be1 + i * DD,
                                                    i * 2 + 0, 0);
        k_gemm_mma<<<PERSIST_GRID, 256, SMEM_TOT>>>(b2 + i * DD, g2 + i * DD, be2 + i * DD,
                                                    i * 2 + 1, 1);
    }

    cudaMemsetAsync(out, 0, (size_t)BB * DD * sizeof(float));
    k_pool<<<(NN + 63) / 64, 256>>>(batch, out);
}